// round 2
// baseline (speedup 1.0000x reference)
#include <cuda_runtime.h>
#include <cuda_bf16.h>

// Problem constants (fixed by the dataset)
#define F_DIM   128
#define OUT_DIM 128
#define HEADS   4
#define DHEAD   32
#define MAXN    10240
#define MAXE    655360
#define ATT_SCALE 0.17677669529663687f   // 1/sqrt(32)
#define LN_EPS  1e-5f
#define NEG_BIG (-1e30f)

// ---------------- scratch (device globals; no allocation allowed) -------------
__device__ float g_Q[MAXN * F_DIM];
__device__ float g_K[MAXN * F_DIM];
__device__ float g_V[MAXN * F_DIM];
__device__ float g_R[MAXN * F_DIM];
__device__ int   g_counts[MAXN];
__device__ int   g_offs[MAXN + 1];
__device__ int   g_cursor[MAXN];
__device__ int   g_srcsorted[MAXE];

// ---------------- K0: zero the histogram --------------------------------------
__global__ void k_zero_counts(int N) {
    int i = blockIdx.x * blockDim.x + threadIdx.x;
    if (i < N) g_counts[i] = 0;
}

// ---------------- K1: fused Q/K/V/R projections --------------------------------
// One block = 16 nodes, 128 threads (thread t = output column c).
// Each thread keeps 16x4 accumulators in registers; X tile staged in shared.
__global__ __launch_bounds__(128) void k_qkvr(
    const float* __restrict__ X,
    const float* __restrict__ WQ, const float* __restrict__ WK,
    const float* __restrict__ WV, const float* __restrict__ WR,
    const float* __restrict__ br, int N)
{
    __shared__ float xs[16][F_DIM];
    const int n0 = blockIdx.x * 16;
    const int t  = threadIdx.x;           // column index 0..127

    #pragma unroll
    for (int i = 0; i < 16; ++i) {
        int n = n0 + i;
        xs[i][t] = (n < N) ? X[n * F_DIM + t] : 0.f;
    }
    __syncthreads();

    float aq[16], ak[16], av[16], ar[16];
    #pragma unroll
    for (int i = 0; i < 16; ++i) { aq[i] = ak[i] = av[i] = ar[i] = 0.f; }

    #pragma unroll 4
    for (int f = 0; f < F_DIM; ++f) {
        const float wq = __ldg(&WQ[f * F_DIM + t]);
        const float wk = __ldg(&WK[f * F_DIM + t]);
        const float wv = __ldg(&WV[f * F_DIM + t]);
        const float wr = __ldg(&WR[f * F_DIM + t]);
        #pragma unroll
        for (int i = 0; i < 16; ++i) {
            const float x = xs[i][f];
            aq[i] = fmaf(x, wq, aq[i]);
            ak[i] = fmaf(x, wk, ak[i]);
            av[i] = fmaf(x, wv, av[i]);
            ar[i] = fmaf(x, wr, ar[i]);
        }
    }

    const float b = __ldg(&br[t]);
    #pragma unroll
    for (int i = 0; i < 16; ++i) {
        const int n = n0 + i;
        if (n < N) {
            g_Q[n * F_DIM + t] = aq[i];
            g_K[n * F_DIM + t] = ak[i];
            g_V[n * F_DIM + t] = av[i];
            g_R[n * F_DIM + t] = ar[i] + b;
        }
    }
}

// ---------------- K2: histogram of dst ----------------------------------------
__global__ void k_hist(const int* __restrict__ dst, int E) {
    int e = blockIdx.x * blockDim.x + threadIdx.x;
    if (e < E) atomicAdd(&g_counts[dst[e]], 1);
}

// ---------------- K3: exclusive scan (single block, 1024 threads) --------------
__global__ __launch_bounds__(1024) void k_scan(int N, int E) {
    __shared__ int part[1024];
    const int t = threadIdx.x;
    const int chunk = (N + 1023) >> 10;
    const int b = t * chunk;
    const int e = min(N, b + chunk);

    int s = 0;
    for (int i = b; i < e; ++i) s += g_counts[i];
    part[t] = s;
    __syncthreads();

    // Hillis-Steele inclusive scan
    for (int o = 1; o < 1024; o <<= 1) {
        int v = 0;
        if (t >= o) v = part[t - o];
        __syncthreads();
        if (t >= o) part[t] += v;
        __syncthreads();
    }

    int run = (t == 0) ? 0 : part[t - 1];
    for (int i = b; i < e; ++i) {
        g_offs[i]   = run;
        g_cursor[i] = run;
        run += g_counts[i];
    }
    if (t == 0) g_offs[N] = E;
}

// ---------------- K4: scatter edges into CSR order -----------------------------
__global__ void k_scatter(const int* __restrict__ src, const int* __restrict__ dst, int E) {
    int e = blockIdx.x * blockDim.x + threadIdx.x;
    if (e < E) {
        int pos = atomicAdd(&g_cursor[dst[e]], 1);
        g_srcsorted[pos] = src[e];
    }
}

// ---------------- K5: fused attention + residual + LayerNorm -------------------
// One warp per destination node. Lane l owns floats [4l, 4l+4) of the 128-wide
// row; head h = l/8. Online softmax in registers; no atomics.
__global__ __launch_bounds__(256) void k_attn(
    const float* __restrict__ gamma, const float* __restrict__ beta,
    float* __restrict__ out, int N)
{
    const int warp = (blockIdx.x * blockDim.x + threadIdx.x) >> 5;
    if (warp >= N) return;
    const int lane = threadIdx.x & 31;

    const float4* __restrict__ Q4 = (const float4*)g_Q;
    const float4* __restrict__ K4 = (const float4*)g_K;
    const float4* __restrict__ V4 = (const float4*)g_V;

    const float4 q = Q4[warp * 32 + lane];
    float4 acc = make_float4(0.f, 0.f, 0.f, 0.f);
    float m = NEG_BIG;
    float ssum = 0.f;

    const int beg = g_offs[warp];
    const int end = g_offs[warp + 1];

    for (int base = beg; base < end; base += 32) {
        const int idx = base + lane;
        const int mysrc = (idx < end) ? g_srcsorted[idx] : 0;
        const int cnt = min(32, end - base);
        for (int j = 0; j < cnt; ++j) {
            const int src = __shfl_sync(0xffffffffu, mysrc, j);
            const float4 k = K4[src * 32 + lane];
            const float4 v = V4[src * 32 + lane];
            // per-head dot product: reduce within 8-lane groups
            float p = q.x * k.x + q.y * k.y + q.z * k.z + q.w * k.w;
            p += __shfl_xor_sync(0xffffffffu, p, 1);
            p += __shfl_xor_sync(0xffffffffu, p, 2);
            p += __shfl_xor_sync(0xffffffffu, p, 4);
            p *= ATT_SCALE;
            // online softmax update (per head; consistent within 8-lane group)
            const float mn   = fmaxf(m, p);
            const float corr = __expf(m - mn);   // m=-1e30 first iter -> 0
            const float w    = __expf(p - mn);
            m = mn;
            ssum = ssum * corr + w;
            acc.x = fmaf(w, v.x, acc.x * corr);
            acc.y = fmaf(w, v.y, acc.y * corr);
            acc.z = fmaf(w, v.z, acc.z * corr);
            acc.w = fmaf(w, v.w, acc.w * corr);
        }
    }

    const float inv = 1.f / (ssum + 1e-12f);   // matches reference alpha = ex/(sm+1e-12)
    const float4 r = ((const float4*)g_R)[warp * 32 + lane];
    float4 h;
    h.x = fmaf(acc.x, inv, r.x);
    h.y = fmaf(acc.y, inv, r.y);
    h.z = fmaf(acc.z, inv, r.z);
    h.w = fmaf(acc.w, inv, r.w);

    // LayerNorm over the 128 values held across the warp
    float s1 = h.x + h.y + h.z + h.w;
    float s2 = h.x * h.x + h.y * h.y + h.z * h.z + h.w * h.w;
    #pragma unroll
    for (int o = 16; o; o >>= 1) {
        s1 += __shfl_xor_sync(0xffffffffu, s1, o);
        s2 += __shfl_xor_sync(0xffffffffu, s2, o);
    }
    const float mu  = s1 * (1.f / 128.f);
    const float var = s2 * (1.f / 128.f) - mu * mu;
    const float rs  = rsqrtf(var + LN_EPS);

    const float4 g = ((const float4*)gamma)[lane];
    const float4 b = ((const float4*)beta)[lane];
    float4 o4;
    o4.x = fmaf(g.x * (h.x - mu), rs, b.x);
    o4.y = fmaf(g.y * (h.y - mu), rs, b.y);
    o4.z = fmaf(g.z * (h.z - mu), rs, b.z);
    o4.w = fmaf(g.w * (h.w - mu), rs, b.w);
    ((float4*)out)[warp * 32 + lane] = o4;
}

// ---------------- launch -------------------------------------------------------
extern "C" void kernel_launch(void* const* d_in, const int* in_sizes, int n_in,
                              void* d_out, int out_size)
{
    const float* nodes = (const float*)d_in[0];
    const float* WQ    = (const float*)d_in[1];
    const float* WK    = (const float*)d_in[2];
    const float* WV    = (const float*)d_in[3];
    const float* WR    = (const float*)d_in[4];
    const float* br    = (const float*)d_in[5];
    const float* gamma = (const float*)d_in[6];
    const float* beta  = (const float*)d_in[7];
    const int*   ei    = (const int*)d_in[8];

    const int N = in_sizes[0] / F_DIM;
    const int E = in_sizes[8] / 2;
    const int* src = ei;
    const int* dst = ei + E;

    k_zero_counts<<<(N + 255) / 256, 256>>>(N);
    k_qkvr<<<(N + 15) / 16, 128>>>(nodes, WQ, WK, WV, WR, br, N);
    k_hist<<<(E + 255) / 256, 256>>>(dst, E);
    k_scan<<<1, 1024>>>(N, E);
    k_scatter<<<(E + 255) / 256, 256>>>(src, dst, E);
    k_attn<<<(N + 7) / 8, 256>>>(gamma, beta, (float*)d_out, N);
}

// round 3
// speedup vs baseline: 1.1189x; 1.1189x over previous
#include <cuda_runtime.h>
#include <cuda_fp16.h>

// Problem constants (fixed by the dataset)
#define F_DIM   128
#define MAXN    10240
#define MAXE    655360
#define ATT_SCALE 0.17677669529663687f   // 1/sqrt(32)
#define LN_EPS  1e-5f

// ---------------- scratch (device globals; no allocation allowed) -------------
__device__ float  g_Q[MAXN * F_DIM];
__device__ __half g_KV[MAXN * 256];      // per node: 128 K halfs then 128 V halfs
__device__ float  g_R[MAXN * F_DIM];
__device__ int    g_counts[MAXN];
__device__ int    g_offs[MAXN + 1];
__device__ int    g_cursor[MAXN];
__device__ int    g_srcsorted[MAXE];

// ---------------- packed fp32x2 helpers (Blackwell) ----------------------------
__device__ __forceinline__ unsigned long long fma2(
    unsigned long long a, unsigned long long b, unsigned long long c) {
    unsigned long long d;
    asm("fma.rn.f32x2 %0, %1, %2, %3;" : "=l"(d) : "l"(a), "l"(b), "l"(c));
    return d;
}
__device__ __forceinline__ unsigned long long pack2(float lo, float hi) {
    unsigned long long d;
    asm("mov.b64 %0, {%1, %2};" : "=l"(d) : "f"(lo), "f"(hi));
    return d;
}
__device__ __forceinline__ void unpack2(unsigned long long v, float& lo, float& hi) {
    asm("mov.b64 {%0, %1}, %2;" : "=f"(lo), "=f"(hi) : "l"(v));
}

// ---------------- K0: zero the histogram --------------------------------------
__global__ void k_zero_counts(int N) {
    int i = blockIdx.x * blockDim.x + threadIdx.x;
    if (i < N) g_counts[i] = 0;
}

// ---------------- K1: fused Q/K/V/R projections + dst histogram ----------------
// One block = 16 nodes, 128 threads (thread t = output column).
// Accumulators held as packed f32x2 pairs (nodes 2j, 2j+1); FFMA2 inner loop.
// After the GEMM, the block histograms its slice of dst (overlaps atomics).
__global__ __launch_bounds__(128) void k_qkvr(
    const float* __restrict__ X,
    const float* __restrict__ WQ, const float* __restrict__ WK,
    const float* __restrict__ WV, const float* __restrict__ WR,
    const float* __restrict__ br,
    const int* __restrict__ dst, int N, int E, int epb)
{
    __shared__ float xs[F_DIM][16];      // xs[f][i] = X[n0+i][f]
    const int n0 = blockIdx.x * 16;
    const int t  = threadIdx.x;          // output column 0..127

    #pragma unroll
    for (int i = 0; i < 16; ++i) {
        int n = n0 + i;
        xs[t][i] = (n < N) ? X[n * F_DIM + t] : 0.f;
    }
    __syncthreads();

    unsigned long long aq[8], ak[8], av[8], ar[8];
    #pragma unroll
    for (int j = 0; j < 8; ++j) { aq[j] = ak[j] = av[j] = ar[j] = 0ull; }

    #pragma unroll 4
    for (int f = 0; f < F_DIM; ++f) {
        const float wq = __ldg(&WQ[f * F_DIM + t]);
        const float wk = __ldg(&WK[f * F_DIM + t]);
        const float wv = __ldg(&WV[f * F_DIM + t]);
        const float wr = __ldg(&WR[f * F_DIM + t]);
        const unsigned long long wq2 = pack2(wq, wq);
        const unsigned long long wk2 = pack2(wk, wk);
        const unsigned long long wv2 = pack2(wv, wv);
        const unsigned long long wr2 = pack2(wr, wr);
        #pragma unroll
        for (int j = 0; j < 8; ++j) {
            const unsigned long long x2 =
                *reinterpret_cast<const unsigned long long*>(&xs[f][2 * j]);
            aq[j] = fma2(x2, wq2, aq[j]);
            ak[j] = fma2(x2, wk2, ak[j]);
            av[j] = fma2(x2, wv2, av[j]);
            ar[j] = fma2(x2, wr2, ar[j]);
        }
    }

    const float b = __ldg(&br[t]);
    #pragma unroll
    for (int j = 0; j < 8; ++j) {
        float qlo, qhi, klo, khi, vlo, vhi, rlo, rhi;
        unpack2(aq[j], qlo, qhi);
        unpack2(ak[j], klo, khi);
        unpack2(av[j], vlo, vhi);
        unpack2(ar[j], rlo, rhi);
        const int nA = n0 + 2 * j, nB = nA + 1;
        if (nA < N) {
            g_Q[nA * F_DIM + t]   = qlo;
            g_KV[nA * 256 + t]       = __float2half_rn(klo);
            g_KV[nA * 256 + 128 + t] = __float2half_rn(vlo);
            g_R[nA * F_DIM + t]   = rlo + b;
        }
        if (nB < N) {
            g_Q[nB * F_DIM + t]   = qhi;
            g_KV[nB * 256 + t]       = __float2half_rn(khi);
            g_KV[nB * 256 + 128 + t] = __float2half_rn(vhi);
            g_R[nB * F_DIM + t]   = rhi + b;
        }
    }

    // fused dst histogram: this block's edge slice
    const int e0 = blockIdx.x * epb;
    const int e1 = min(e0 + epb, E);
    for (int e = e0 + t; e < e1; e += 128)
        atomicAdd(&g_counts[dst[e]], 1);
}

// ---------------- K2: exclusive scan (warp-shuffle, 2 barriers) ----------------
__global__ __launch_bounds__(1024) void k_scan(int N, int E) {
    __shared__ int wsum[32];
    const int t = threadIdx.x;
    const int lane = t & 31, w = t >> 5;
    const int base = t * 10;             // 1024*10 = 10240 >= MAXN

    int loc[10];
    int s = 0;
    #pragma unroll
    for (int i = 0; i < 10; ++i) {
        const int idx = base + i;
        loc[i] = (idx < N) ? g_counts[idx] : 0;
        s += loc[i];
    }
    // warp inclusive scan
    int inc = s;
    #pragma unroll
    for (int o = 1; o < 32; o <<= 1) {
        int v = __shfl_up_sync(0xffffffffu, inc, o);
        if (lane >= o) inc += v;
    }
    if (lane == 31) wsum[w] = inc;
    __syncthreads();
    if (w == 0) {
        int v = wsum[lane];
        #pragma unroll
        for (int o = 1; o < 32; o <<= 1) {
            int u = __shfl_up_sync(0xffffffffu, v, o);
            if (lane >= o) v += u;
        }
        wsum[lane] = v;
    }
    __syncthreads();
    int run = ((w == 0) ? 0 : wsum[w - 1]) + (inc - s);  // exclusive prefix
    #pragma unroll
    for (int i = 0; i < 10; ++i) {
        const int idx = base + i;
        if (idx < N) { g_offs[idx] = run; g_cursor[idx] = run; run += loc[i]; }
    }
    if (t == 0) g_offs[N] = E;
}

// ---------------- K3: scatter edges into CSR order -----------------------------
__global__ void k_scatter(const int* __restrict__ src, const int* __restrict__ dst, int E) {
    int e = blockIdx.x * blockDim.x + threadIdx.x;
    if (e < E) {
        int pos = atomicAdd(&g_cursor[dst[e]], 1);
        g_srcsorted[pos] = src[e];
    }
}

// ---------------- K4: fused attention + residual + LayerNorm -------------------
// One warp per destination node; lane l owns dims [4l, 4l+4); head = l/8.
// exp without max subtraction (scores bounded; max cancels in alpha).
__global__ __launch_bounds__(256) void k_attn(
    const float* __restrict__ gamma, const float* __restrict__ beta,
    float* __restrict__ out, int N)
{
    const int warp = (blockIdx.x * blockDim.x + threadIdx.x) >> 5;
    if (warp >= N) return;
    const int lane = threadIdx.x & 31;

    float4 q = ((const float4*)g_Q)[warp * 32 + lane];
    q.x *= ATT_SCALE; q.y *= ATT_SCALE; q.z *= ATT_SCALE; q.w *= ATT_SCALE;

    const uint2* __restrict__ KV = (const uint2*)g_KV;   // 64 uint2 per node row

    float4 acc = make_float4(0.f, 0.f, 0.f, 0.f);
    float ssum = 0.f;

    const int beg = g_offs[warp];
    const int end = g_offs[warp + 1];

    for (int base = beg; base < end; base += 32) {
        const int idx = base + lane;
        const int mysrc = (idx < end) ? g_srcsorted[idx] : 0;
        const int cnt = min(32, end - base);
        for (int j = 0; j < cnt; ++j) {
            const int src = __shfl_sync(0xffffffffu, mysrc, j);
            const uint2 ku = KV[src * 64 + lane];
            const uint2 vu = KV[src * 64 + 32 + lane];
            const float2 k0 = __half22float2(*(const __half2*)&ku.x);
            const float2 k1 = __half22float2(*(const __half2*)&ku.y);
            // per-head dot: reduce within 8-lane groups
            float p = q.x * k0.x + q.y * k0.y + q.z * k1.x + q.w * k1.y;
            p += __shfl_xor_sync(0xffffffffu, p, 1);
            p += __shfl_xor_sync(0xffffffffu, p, 2);
            p += __shfl_xor_sync(0xffffffffu, p, 4);
            const float wgt = __expf(p);
            const float2 v0 = __half22float2(*(const __half2*)&vu.x);
            const float2 v1 = __half22float2(*(const __half2*)&vu.y);
            ssum += wgt;
            acc.x = fmaf(wgt, v0.x, acc.x);
            acc.y = fmaf(wgt, v0.y, acc.y);
            acc.z = fmaf(wgt, v1.x, acc.z);
            acc.w = fmaf(wgt, v1.y, acc.w);
        }
    }

    const float inv = 1.f / (ssum + 1e-12f);
    const float4 r = ((const float4*)g_R)[warp * 32 + lane];
    float4 h;
    h.x = fmaf(acc.x, inv, r.x);
    h.y = fmaf(acc.y, inv, r.y);
    h.z = fmaf(acc.z, inv, r.z);
    h.w = fmaf(acc.w, inv, r.w);

    // LayerNorm over the 128 values held across the warp
    float s1 = h.x + h.y + h.z + h.w;
    float s2 = h.x * h.x + h.y * h.y + h.z * h.z + h.w * h.w;
    #pragma unroll
    for (int o = 16; o; o >>= 1) {
        s1 += __shfl_xor_sync(0xffffffffu, s1, o);
        s2 += __shfl_xor_sync(0xffffffffu, s2, o);
    }
    const float mu  = s1 * (1.f / 128.f);
    const float var = s2 * (1.f / 128.f) - mu * mu;
    const float rs  = rsqrtf(var + LN_EPS);

    const float4 g = ((const float4*)gamma)[lane];
    const float4 b = ((const float4*)beta)[lane];
    float4 o4;
    o4.x = fmaf(g.x * (h.x - mu), rs, b.x);
    o4.y = fmaf(g.y * (h.y - mu), rs, b.y);
    o4.z = fmaf(g.z * (h.z - mu), rs, b.z);
    o4.w = fmaf(g.w * (h.w - mu), rs, b.w);
    ((float4*)out)[warp * 32 + lane] = o4;
}

// ---------------- launch -------------------------------------------------------
extern "C" void kernel_launch(void* const* d_in, const int* in_sizes, int n_in,
                              void* d_out, int out_size)
{
    const float* nodes = (const float*)d_in[0];
    const float* WQ    = (const float*)d_in[1];
    const float* WK    = (const float*)d_in[2];
    const float* WV    = (const float*)d_in[3];
    const float* WR    = (const float*)d_in[4];
    const float* br    = (const float*)d_in[5];
    const float* gamma = (const float*)d_in[6];
    const float* beta  = (const float*)d_in[7];
    const int*   ei    = (const int*)d_in[8];

    const int N = in_sizes[0] / F_DIM;
    const int E = in_sizes[8] / 2;
    const int* src = ei;
    const int* dst = ei + E;

    const int nblk = (N + 15) / 16;
    const int epb  = (E + nblk - 1) / nblk;

    k_zero_counts<<<(N + 255) / 256, 256>>>(N);
    k_qkvr<<<nblk, 128>>>(nodes, WQ, WK, WV, WR, br, dst, N, E, epb);
    k_scan<<<1, 1024>>>(N, E);
    k_scatter<<<(E + 255) / 256, 256>>>(src, dst, E);
    k_attn<<<(N + 7) / 8, 256>>>(gamma, beta, (float*)d_out, N);
}